// round 15
// baseline (speedup 1.0000x reference)
#include <cuda_runtime.h>
#include <cuda_bf16.h>
#include <math.h>
#include <stdint.h>

#define NN 50000
#define EE 600000
#define HH 128
#define GG 64
#define PCH 64
#define DCAP 64
#define NTILES 391   // ceil(50000/128)

// ---- static device scratch ----
__device__ float g_bufA[(size_t)NN * HH];
__device__ float g_pool[GG * HH];
__device__ int   g_deg[3 * NN];                 // zeroed at load; re-zeroed by pool_kernel
__device__ int   g_csr[(size_t)3 * NN * DCAP];
// int8 2-level feature buffers (ping-pong) + agg + per-row scales
__device__ int8_t g_hq1[2][(size_t)NN * HH];
__device__ int8_t g_hq2[2][(size_t)NN * HH];
__device__ float  g_rsH[2][NN];
__device__ int8_t g_aq1[(size_t)NN * HH];
__device__ int8_t g_aq2[(size_t)NN * HH];
__device__ float  g_rsA[NN];
// weights int8: [conv 5][phase 2][lvl 2][n=128][k=128]; per-col scales [cv][ph][n]
__device__ int8_t g_wq[5 * 4 * HH * HH];
__device__ float  g_csB[5 * 2 * HH];

// ================= helpers =================
__device__ __forceinline__ uint32_t s2u(const void* p) {
    uint32_t a;
    asm("{ .reg .u64 t; cvta.to.shared.u64 t, %1; cvt.u32.u64 %0, t; }" : "=r"(a) : "l"(p));
    return a;
}
__device__ __forceinline__ void cpa16(uint32_t d, const void* s, uint32_t ssz) {
    asm volatile("cp.async.cg.shared.global [%0], [%1], 16, %2;"
                 :: "r"(d), "l"(s), "r"(ssz) : "memory");
}
__device__ __forceinline__ void cpa_commit() {
    asm volatile("cp.async.commit_group;" ::: "memory");
}
template <int N>
__device__ __forceinline__ void cpa_wait() {
    asm volatile("cp.async.wait_group %0;" :: "n"(N) : "memory");
}
#define LDSM4(r0, r1, r2, r3, a) \
    asm volatile("ldmatrix.sync.aligned.m8n8.x4.shared.b16 {%0,%1,%2,%3}, [%4];" \
                 : "=r"(r0), "=r"(r1), "=r"(r2), "=r"(r3) : "r"(a))
#define MMA_S8(c, a, b) \
    asm volatile("mma.sync.aligned.m16n8k32.row.col.s32.s8.s8.s32 " \
                 "{%0,%1,%2,%3},{%4,%5,%6,%7},{%8,%9},{%0,%1,%2,%3};" \
                 : "+r"((c)[0]), "+r"((c)[1]), "+r"((c)[2]), "+r"((c)[3]) \
                 : "r"((a)[0]), "r"((a)[1]), "r"((a)[2]), "r"((a)[3]), \
                   "r"((b)[0]), "r"((b)[1]))

__device__ __forceinline__ int q8i(float v, float s) {
    int q = __float2int_rn(v * s);
    return max(-127, min(127, q));
}

// smem: B 4x16KB @0, A 3 bufs x 32KB @65536, ssred/ssmax @163840
#define SM_B 0
#define SM_A 65536
#define SM_SS 163840
#define SMEMSZ 167936

// ---------------- fused setup: bucketed CSR + x->int8 2-level + weight quant ----------------
struct WPtrs { const float* Wl[5]; const float* Wr[5]; };
#define CB 7032
#define XQ 6250
#define WQ 160
__global__ __launch_bounds__(256) void setup_kernel(const int* __restrict__ e0,
                                                    const int* __restrict__ e1,
                                                    const int* __restrict__ e2,
                                                    WPtrs wp,
                                                    const float* __restrict__ x,
                                                    int8_t* __restrict__ oq1,
                                                    int8_t* __restrict__ oq2,
                                                    float* __restrict__ orsc,
                                                    int8_t* __restrict__ wq,
                                                    float* __restrict__ csb,
                                                    int* __restrict__ deg,
                                                    int* __restrict__ csr) {
    int b = blockIdx.x, tid = threadIdx.x;
    int lane = tid & 31, wid = tid >> 5;
    if (b < CB) {
        int t = b * 256 + tid;
        if (t < 3 * EE) {
            int s = t / EE, i = t - s * EE;
            const int* e = (s == 0) ? e0 : ((s == 1) ? e1 : e2);
            int dst = e[EE + i];
            int p = atomicAdd(&deg[s * NN + dst], 1);
            if (p < DCAP) csr[((size_t)s * NN + dst) * DCAP + p] = e[i];
        }
    } else if (b < CB + XQ) {
        // warp per row: quantize x into 2-level int8 + per-row scale
        int row = (b - CB) * 8 + wid;
        float4 v = *(const float4*)(x + (size_t)row * HH + lane * 4);
        float m = fmaxf(fmaxf(fabsf(v.x), fabsf(v.y)), fmaxf(fabsf(v.z), fabsf(v.w)));
#pragma unroll
        for (int o = 16; o > 0; o >>= 1) m = fmaxf(m, __shfl_xor_sync(0xffffffffu, m, o));
        float s = (m > 0.f) ? 127.f / m : 0.f;
        float st = (m > 0.f) ? m / 127.f : 0.f;
        int q0 = q8i(v.x, s), q1 = q8i(v.y, s), q2 = q8i(v.z, s), q3 = q8i(v.w, s);
        float s2 = s * 127.f;
        int r0 = q8i(v.x - q0 * st, s2), r1 = q8i(v.y - q1 * st, s2);
        int r2 = q8i(v.z - q2 * st, s2), r3 = q8i(v.w - q3 * st, s2);
        uint32_t p1 = (q0 & 255) | ((q1 & 255) << 8) | ((q2 & 255) << 16) | ((uint32_t)(q3 & 255) << 24);
        uint32_t p2 = (r0 & 255) | ((r1 & 255) << 8) | ((r2 & 255) << 16) | ((uint32_t)(r3 & 255) << 24);
        *(uint32_t*)(oq1 + (size_t)row * HH + lane * 4) = p1;
        *(uint32_t*)(oq2 + (size_t)row * HH + lane * 4) = p2;
        if (lane == 0) orsc[row] = st;
    } else if (b < CB + XQ + WQ) {
        // warp per (cv, ph, n): quantize weight column (transposed) 2-level int8
        int w = (b - CB - XQ) * 8 + wid;   // 0..1279
        int cv = w >> 8, rem = w & 255;
        int ph = rem >> 7, n = rem & 127;
        const float* W = ph ? wp.Wr[cv] : wp.Wl[cv];
        float v[4];
#pragma unroll
        for (int j = 0; j < 4; j++) v[j] = W[(lane * 4 + j) * HH + n];
        float m = fmaxf(fmaxf(fabsf(v[0]), fabsf(v[1])), fmaxf(fabsf(v[2]), fabsf(v[3])));
#pragma unroll
        for (int o = 16; o > 0; o >>= 1) m = fmaxf(m, __shfl_xor_sync(0xffffffffu, m, o));
        float s = (m > 0.f) ? 127.f / m : 0.f;
        float st = (m > 0.f) ? m / 127.f : 0.f;
        int q[4], r[4];
#pragma unroll
        for (int j = 0; j < 4; j++) {
            q[j] = q8i(v[j], s);
            r[j] = q8i(v[j] - q[j] * st, s * 127.f);
        }
        uint32_t p1 = (q[0] & 255) | ((q[1] & 255) << 8) | ((q[2] & 255) << 16) | ((uint32_t)(q[3] & 255) << 24);
        uint32_t p2 = (r[0] & 255) | ((r[1] & 255) << 8) | ((r[2] & 255) << 16) | ((uint32_t)(r[3] & 255) << 24);
        size_t base = ((size_t)(cv * 2 + ph) * 2) * (HH * HH);
        *(uint32_t*)(wq + base + n * HH + lane * 4) = p1;
        *(uint32_t*)(wq + base + HH * HH + n * HH + lane * 4) = p2;
        if (lane == 0) csb[cv * 256 + ph * 128 + n] = st;
    }
}

// ---------------- pool zero ----------------
__global__ void zpool_kernel(float* __restrict__ poolp) {
    poolp[blockIdx.x * 256 + threadIdx.x] = 0.f;
}

// ---------------- mean aggregation: fp32 gather + int8 2-level quant epilogue ----------------
__global__ __launch_bounds__(256) void agg_kernel(const float* __restrict__ fsrc,
                                                  int8_t* __restrict__ aq1,
                                                  int8_t* __restrict__ aq2,
                                                  float* __restrict__ rsA,
                                                  const int* __restrict__ csr,
                                                  const int* __restrict__ deg) {
    int node = blockIdx.x * 8 + (threadIdx.x >> 5);
    if (node >= NN) return;
    int lane = threadIdx.x & 31;
    int co = lane * 4;
    int d = deg[node];
    int dr = min(d, DCAP);
    const int* nb = csr + (size_t)node * DCAP;
    float4 acc = make_float4(0.f, 0.f, 0.f, 0.f);

    int p = 0;
    for (; p + 4 <= dr; p += 4) {
        int4 iv = *(const int4*)(nb + p);
        float4 v0 = *(const float4*)(fsrc + (size_t)iv.x * HH + co);
        float4 v1 = *(const float4*)(fsrc + (size_t)iv.y * HH + co);
        float4 v2 = *(const float4*)(fsrc + (size_t)iv.z * HH + co);
        float4 v3 = *(const float4*)(fsrc + (size_t)iv.w * HH + co);
        acc.x += v0.x + v1.x + v2.x + v3.x;
        acc.y += v0.y + v1.y + v2.y + v3.y;
        acc.z += v0.z + v1.z + v2.z + v3.z;
        acc.w += v0.w + v1.w + v2.w + v3.w;
    }
    for (; p < dr; ++p) {
        float4 v0 = *(const float4*)(fsrc + (size_t)nb[p] * HH + co);
        acc.x += v0.x; acc.y += v0.y; acc.z += v0.z; acc.w += v0.w;
    }
    float inv = 1.f / fmaxf((float)d, 1.f);
    acc.x *= inv; acc.y *= inv; acc.z *= inv; acc.w *= inv;

    float m = fmaxf(fmaxf(fabsf(acc.x), fabsf(acc.y)), fmaxf(fabsf(acc.z), fabsf(acc.w)));
#pragma unroll
    for (int o = 16; o > 0; o >>= 1) m = fmaxf(m, __shfl_xor_sync(0xffffffffu, m, o));
    float s = (m > 0.f) ? 127.f / m : 0.f;
    float st = (m > 0.f) ? m / 127.f : 0.f;
    int q0 = q8i(acc.x, s), q1 = q8i(acc.y, s), q2 = q8i(acc.z, s), q3 = q8i(acc.w, s);
    float s2 = s * 127.f;
    int r0 = q8i(acc.x - q0 * st, s2), r1 = q8i(acc.y - q1 * st, s2);
    int r2 = q8i(acc.z - q2 * st, s2), r3 = q8i(acc.w - q3 * st, s2);
    uint32_t p1 = (q0 & 255) | ((q1 & 255) << 8) | ((q2 & 255) << 16) | ((uint32_t)(q3 & 255) << 24);
    uint32_t p2 = (r0 & 255) | ((r1 & 255) << 8) | ((r2 & 255) << 16) | ((uint32_t)(r3 & 255) << 24);
    *(uint32_t*)(aq1 + (size_t)node * HH + co) = p1;
    *(uint32_t*)(aq2 + (size_t)node * HH + co) = p2;
    if (lane == 0) rsA[node] = st;
}

// ---------------- persistent int8 2-level tensor-core SAGE GEMM, 512 threads ----------------
// Per tile: 2 phases (agg@Wl, h@Wr), each K=128. Per phase: 3 sequential products
// (q1q1, q1q2, q2q1) through one int32 accumulator set, scaled into fp32 acc.
__global__ __launch_bounds__(512) void sage_mma(const int8_t* __restrict__ aq1,
                                                const int8_t* __restrict__ aq2,
                                                const float* __restrict__ rsA,
                                                const int8_t* __restrict__ hq1,
                                                const int8_t* __restrict__ hq2,
                                                const float* __restrict__ rsH,
                                                const int8_t* __restrict__ wq,
                                                const float* __restrict__ csb,
                                                const float* __restrict__ bias,
                                                float* __restrict__ outF,
                                                int8_t* __restrict__ oq1,
                                                int8_t* __restrict__ oq2,
                                                float* __restrict__ rsO,
                                                int doNorm, int writeB) {
    extern __shared__ char smem[];
    const uint32_t sb = s2u(smem);
    const int tid = threadIdx.x;
    const int wid = tid >> 5, lane = tid & 31;
    const int wm = wid >> 2, wn = wid & 3;
    const int bid = blockIdx.x;
    const int nch = 2 * ((NTILES - bid + 147) / 148);

    // B load: 4 matrices (ph,lvl) x 16KB, swizzled [n][128B rows]
#pragma unroll
    for (int i = 0; i < 8; i++) {
        int idx = tid + i * 512;
        int mat = idx >> 10, u = idx & 1023;
        int n = u >> 3, ku = u & 7;
        uint32_t off = (uint32_t)(n * 128 + ku * 16);
        uint32_t sw = off ^ ((off >> 3) & 0x70);
        cpa16(sb + SM_B + mat * 16384 + sw, wq + (size_t)mat * 16384 + n * 128 + ku * 16, 16u);
    }
    auto issueA = [&](int ch) {
        int tile = bid + (ch >> 1) * 148;
        int ph = ch & 1, buf = ch % 3;
        int m0 = tile * 128;
        const int8_t* s1 = ph ? hq1 : aq1;
        const int8_t* s2 = ph ? hq2 : aq2;
#pragma unroll
        for (int i = 0; i < 4; i++) {
            int idx = tid + i * 512;       // 0..2047
            int lvl = idx >> 10, u = idx & 1023;
            int r = u >> 3, ku = u & 7;
            int gm = m0 + r;
            uint32_t off = (uint32_t)(r * 128 + ku * 16);
            uint32_t sw = off ^ ((off >> 3) & 0x70);
            uint32_t ssz = (gm < NN) ? 16u : 0u;
            int gmc = (gm < NN) ? gm : 0;
            const int8_t* src = (lvl ? s2 : s1) + (size_t)gmc * HH + ku * 16;
            cpa16(sb + SM_A + buf * 32768 + lvl * 16384 + sw, src, ssz);
        }
    };
    issueA(0); cpa_commit();
    issueA(1); cpa_commit();

    float facc[2][4][4];
    float* ssred = (float*)(smem + SM_SS);
    float* ssmax = (float*)(smem + SM_SS + 2048);

    const uint32_t rAl = (uint32_t)(wm * 32 + (lane & 15));
    const uint32_t kAl = (uint32_t)((lane >> 4) * 16);
    const uint32_t nBl = (uint32_t)(wn * 32 + ((lane >> 4) << 3) + (lane & 7));
    const uint32_t kBl = (uint32_t)(((lane >> 3) & 1) * 16);

    for (int ch = 0; ch < nch; ch++) {
        if (ch + 2 < nch) cpa_wait<1>(); else cpa_wait<0>();
        __syncthreads();
        if (ch + 2 < nch) { issueA(ch + 2); cpa_commit(); }

        const int buf = ch % 3, ph = ch & 1;
        const int tile = bid + (ch >> 1) * 148;
        const int m0 = tile * 128;
        const uint32_t Abase = sb + SM_A + buf * 32768;
        const uint32_t Bbase = sb + SM_B + ph * 32768;

        if (ph == 0) {
#pragma unroll
            for (int mf = 0; mf < 2; mf++)
#pragma unroll
                for (int nf = 0; nf < 4; nf++)
#pragma unroll
                    for (int q = 0; q < 4; q++) facc[mf][nf][q] = 0.f;
        }

        // per-row A scales (4 rows per thread) and per-col B scales (8 cols)
        const float* rsx = ph ? rsH : rsA;
        float rs[2][2];
#pragma unroll
        for (int mf = 0; mf < 2; mf++)
#pragma unroll
            for (int hh = 0; hh < 2; hh++) {
                int r = m0 + wm * 32 + mf * 16 + (lane >> 2) + hh * 8;
                rs[mf][hh] = (r < NN) ? __ldg(rsx + r) : 0.f;
            }
        float cbv[4][2];
#pragma unroll
        for (int nf = 0; nf < 4; nf++) {
            int col = wn * 32 + nf * 8 + (lane & 3) * 2;
            cbv[nf][0] = __ldg(csb + ph * 128 + col);
            cbv[nf][1] = __ldg(csb + ph * 128 + col + 1);
        }

#pragma unroll
        for (int prod = 0; prod < 3; prod++) {
            const int ia = (prod == 2), ib = (prod == 1);
            const uint32_t Ab = Abase + ia * 16384;
            const uint32_t Bb = Bbase + ib * 16384;
            int pacc[2][4][4];
#pragma unroll
            for (int mf = 0; mf < 2; mf++)
#pragma unroll
                for (int nf = 0; nf < 4; nf++)
#pragma unroll
                    for (int q = 0; q < 4; q++) pacc[mf][nf][q] = 0;
#pragma unroll
            for (int s = 0; s < 4; s++) {
                uint32_t kb = s * 32;
                uint32_t af[2][4], bf[4][2];
#pragma unroll
                for (int mf = 0; mf < 2; mf++) {
                    uint32_t off = (rAl + mf * 16) * 128 + kb + kAl;
                    uint32_t sw = off ^ ((off >> 3) & 0x70);
                    LDSM4(af[mf][0], af[mf][1], af[mf][2], af[mf][3], Ab + sw);
                }
#pragma unroll
                for (int np = 0; np < 2; np++) {
                    uint32_t off = (nBl + np * 16) * 128 + kb + kBl;
                    uint32_t sw = off ^ ((off >> 3) & 0x70);
                    uint32_t r0, r1, r2, r3;
                    LDSM4(r0, r1, r2, r3, Bb + sw);
                    bf[2 * np][0] = r0; bf[2 * np][1] = r1;
                    bf[2 * np + 1][0] = r2; bf[2 * np + 1][1] = r3;
                }
#pragma unroll
                for (int mf = 0; mf < 2; mf++)
#pragma unroll
                    for (int nf = 0; nf < 4; nf++)
                        MMA_S8(pacc[mf][nf], af[mf], bf[nf]);
            }
            const float il = 1.f / 127.f;
#pragma unroll
            for (int mf = 0; mf < 2; mf++)
#pragma unroll
                for (int hh = 0; hh < 2; hh++) {
                    float ca = ia ? rs[mf][hh] * il : rs[mf][hh];
#pragma unroll
                    for (int nf = 0; nf < 4; nf++) {
                        float c0 = ca * (ib ? cbv[nf][0] * il : cbv[nf][0]);
                        float c1 = ca * (ib ? cbv[nf][1] * il : cbv[nf][1]);
                        facc[mf][nf][2 * hh]     += (float)pacc[mf][nf][2 * hh] * c0;
                        facc[mf][nf][2 * hh + 1] += (float)pacc[mf][nf][2 * hh + 1] * c1;
                    }
                }
        }

        if (ph == 1) {
            // ---------------- epilogue ----------------
            float bc[4][2];
#pragma unroll
            for (int nf = 0; nf < 4; nf++) {
                int col = wn * 32 + nf * 8 + (lane & 3) * 2;
                bc[nf][0] = __ldg(bias + col);
                bc[nf][1] = __ldg(bias + col + 1);
            }
#pragma unroll
            for (int mf = 0; mf < 2; mf++)
#pragma unroll
                for (int nf = 0; nf < 4; nf++) {
                    facc[mf][nf][0] += bc[nf][0];
                    facc[mf][nf][1] += bc[nf][1];
                    facc[mf][nf][2] += bc[nf][0];
                    facc[mf][nf][3] += bc[nf][1];
                }
            // row reductions: sumsq (for norm) and absmax (for quant)
#pragma unroll
            for (int mf = 0; mf < 2; mf++) {
                float s0 = 0.f, s1 = 0.f, m0v = 0.f, m1v = 0.f;
#pragma unroll
                for (int nf = 0; nf < 4; nf++) {
                    s0 += facc[mf][nf][0] * facc[mf][nf][0] + facc[mf][nf][1] * facc[mf][nf][1];
                    s1 += facc[mf][nf][2] * facc[mf][nf][2] + facc[mf][nf][3] * facc[mf][nf][3];
                    m0v = fmaxf(m0v, fmaxf(fabsf(facc[mf][nf][0]), fabsf(facc[mf][nf][1])));
                    m1v = fmaxf(m1v, fmaxf(fabsf(facc[mf][nf][2]), fabsf(facc[mf][nf][3])));
                }
#pragma unroll
                for (int o = 1; o <= 2; o <<= 1) {
                    s0 += __shfl_xor_sync(0xffffffffu, s0, o);
                    s1 += __shfl_xor_sync(0xffffffffu, s1, o);
                    m0v = fmaxf(m0v, __shfl_xor_sync(0xffffffffu, m0v, o));
                    m1v = fmaxf(m1v, __shfl_xor_sync(0xffffffffu, m1v, o));
                }
                if ((lane & 3) == 0) {
                    int r = wm * 32 + mf * 16 + (lane >> 2);
                    ssred[r * 4 + wn] = s0;
                    ssred[(r + 8) * 4 + wn] = s1;
                    ssmax[r * 4 + wn] = m0v;
                    ssmax[(r + 8) * 4 + wn] = m1v;
                }
            }
            __syncthreads();
            float scale[2][2], rmax[2][2];
#pragma unroll
            for (int mf = 0; mf < 2; mf++)
#pragma unroll
                for (int hh = 0; hh < 2; hh++) {
                    int r = wm * 32 + mf * 16 + (lane >> 2) + hh * 8;
                    float t = ssred[r * 4] + ssred[r * 4 + 1] + ssred[r * 4 + 2] + ssred[r * 4 + 3];
                    float mm = fmaxf(fmaxf(ssmax[r * 4], ssmax[r * 4 + 1]),
                                     fmaxf(ssmax[r * 4 + 2], ssmax[r * 4 + 3]));
                    float sc = doNorm ? (1.f / fmaxf(sqrtf(t), 1e-12f)) : 1.f;
                    scale[mf][hh] = sc;
                    rmax[mf][hh] = mm * sc;
                }
#pragma unroll
            for (int mf = 0; mf < 2; mf++)
#pragma unroll
                for (int hh = 0; hh < 2; hh++) {
                    int r = m0 + wm * 32 + mf * 16 + (lane >> 2) + hh * 8;
                    if (r < NN) {
                        float sc = scale[mf][hh];
                        float mm = rmax[mf][hh];
                        float qs = (mm > 0.f) ? 127.f / mm : 0.f;
                        float qt = (mm > 0.f) ? mm / 127.f : 0.f;
#pragma unroll
                        for (int nf = 0; nf < 4; nf++) {
                            int col = wn * 32 + nf * 8 + (lane & 3) * 2;
                            float v0 = facc[mf][nf][2 * hh] * sc;
                            float v1 = facc[mf][nf][2 * hh + 1] * sc;
                            *(float2*)(outF + (size_t)r * HH + col) = make_float2(v0, v1);
                            if (writeB) {
                                int a0 = q8i(v0, qs), a1 = q8i(v1, qs);
                                int b0 = q8i(v0 - a0 * qt, qs * 127.f);
                                int b1 = q8i(v1 - a1 * qt, qs * 127.f);
                                *(uint16_t*)(oq1 + (size_t)r * HH + col) =
                                    (uint16_t)((a0 & 255) | ((a1 & 255) << 8));
                                *(uint16_t*)(oq2 + (size_t)r * HH + col) =
                                    (uint16_t)((b0 & 255) | ((b1 & 255) << 8));
                            }
                        }
                        if (writeB && wn == 0 && (lane & 3) == 0) rsO[r] = qt;
                    }
                }
        }
    }
}

// ---------------- global_add_pool (+ re-zero deg for next replay) ----------------
__global__ __launch_bounds__(128) void pool_kernel(const float* __restrict__ h,
                                                   const int* __restrict__ batch,
                                                   float* __restrict__ pool,
                                                   int* __restrict__ deg) {
    int gtid = blockIdx.x * 128 + threadIdx.x;
    for (int i = gtid; i < 3 * NN; i += gridDim.x * 128) deg[i] = 0;
    int c = threadIdx.x;
    int start = blockIdx.x * PCH;
    if (start >= NN) return;
    int end = min(start + PCH, NN);
    int cur = batch[start];
    float acc = 0.f;
    for (int i = start; i < end; ++i) {
        int b = batch[i];
        if (b != cur) { atomicAdd(&pool[cur * HH + c], acc); acc = 0.f; cur = b; }
        acc += h[(size_t)i * HH + c];
    }
    atomicAdd(&pool[cur * HH + c], acc);
}

// ---------------- MLP head ----------------
__global__ __launch_bounds__(256) void mlp_kernel(const float* __restrict__ pool,
                                                  const float* __restrict__ W0, const float* __restrict__ b0,
                                                  const float* __restrict__ W1, const float* __restrict__ b1,
                                                  const float* __restrict__ hW, const float* __restrict__ hb,
                                                  float* __restrict__ out) {
    __shared__ float Gs[GG * HH];
    int tid = threadIdx.x;
    for (int i = tid; i < GG * HH / 4; i += 256)
        ((float4*)Gs)[i] = ((const float4*)pool)[i];
    __syncthreads();
    int c = tid & 127;
    int rb = tid >> 7;
    float s[32];
#pragma unroll
    for (int j = 0; j < 32; j++) s[j] = b0[c];
    for (int k = 0; k < HH; k++) {
        float w = __ldg(W0 + k * HH + c);
#pragma unroll
        for (int j = 0; j < 32; j++) s[j] = fmaf(Gs[(rb + 2 * j) * HH + k], w, s[j]);
    }
    __syncthreads();
#pragma unroll
    for (int j = 0; j < 32; j++) Gs[(rb + 2 * j) * HH + c] = fmaxf(s[j], 0.f);
    __syncthreads();
#pragma unroll
    for (int j = 0; j < 32; j++) s[j] = b1[c];
    for (int k = 0; k < HH; k++) {
        float w = __ldg(W1 + k * HH + c);
#pragma unroll
        for (int j = 0; j < 32; j++) s[j] = fmaf(Gs[(rb + 2 * j) * HH + k], w, s[j]);
    }
    __syncthreads();
#pragma unroll
    for (int j = 0; j < 32; j++) Gs[(rb + 2 * j) * HH + c] = fmaxf(s[j], 0.f);
    __syncthreads();
    if (tid < GG) {
        float acc = hb[0];
        for (int k = 0; k < HH; k++) acc = fmaf(Gs[tid * HH + k], hW[k], acc);
        out[tid] = acc;
    }
}

// ---------------- driver ----------------
extern "C" void kernel_launch(void* const* d_in, const int* in_sizes, int n_in,
                              void* d_out, int out_size) {
    const float* x     = (const float*)d_in[0];
    const int*   eic   = (const int*)d_in[1];
    const int*   eid   = (const int*)d_in[2];
    const int*   eit   = (const int*)d_in[3];
    const int*   batch = (const int*)d_in[4];
    WPtrs wp;
    const float* bl[5];
    for (int i = 0; i < 5; i++) {
        wp.Wl[i] = (const float*)d_in[5 + 3 * i];
        bl[i]    = (const float*)d_in[6 + 3 * i];
        wp.Wr[i] = (const float*)d_in[7 + 3 * i];
    }
    const float* l0W   = (const float*)d_in[20];
    const float* l0b   = (const float*)d_in[21];
    const float* l1W   = (const float*)d_in[22];
    const float* l1b   = (const float*)d_in[23];
    const float* headW = (const float*)d_in[24];
    const float* headb = (const float*)d_in[25];

    void* p;
    cudaGetSymbolAddress(&p, g_bufA); float* bufA = (float*)p;
    cudaGetSymbolAddress(&p, g_pool); float* poolp = (float*)p;
    cudaGetSymbolAddress(&p, g_deg);  int* degp = (int*)p;
    cudaGetSymbolAddress(&p, g_csr);  int* csrp = (int*)p;
    cudaGetSymbolAddress(&p, g_hq1);  int8_t* hq1 = (int8_t*)p;
    cudaGetSymbolAddress(&p, g_hq2);  int8_t* hq2 = (int8_t*)p;
    cudaGetSymbolAddress(&p, g_rsH);  float* rsH = (float*)p;
    cudaGetSymbolAddress(&p, g_aq1);  int8_t* aq1 = (int8_t*)p;
    cudaGetSymbolAddress(&p, g_aq2);  int8_t* aq2 = (int8_t*)p;
    cudaGetSymbolAddress(&p, g_rsA);  float* rsA = (float*)p;
    cudaGetSymbolAddress(&p, g_wq);   int8_t* wqp = (int8_t*)p;
    cudaGetSymbolAddress(&p, g_csB);  float* csbp = (float*)p;

    cudaFuncSetAttribute(sage_mma, cudaFuncAttributeMaxDynamicSharedMemorySize, SMEMSZ);

    size_t bufsz = (size_t)NN * HH;
    // 1: setup (CSR + x-quant into slot 1 + weight quant); 2: pool zero
    setup_kernel<<<CB + XQ + WQ, 256>>>(eid, eic, eit, wp, x,
                                        hq1 + bufsz, hq2 + bufsz, rsH + NN,
                                        wqp, csbp, degp, csrp);
    zpool_kernel<<<GG * HH / 256, 256>>>(poolp);

    const int Les[7] = {0, 1, 1, 2, 0, 1, 1};
    const int Lcv[7] = {0, 1, 1, 2, 3, 4, 4};
    const int Lnm[7] = {1, 1, 1, 0, 1, 1, 1};

    const float* curF = x;
    for (int li = 0; li < 7; ++li) {
        int es = Les[li], cv = Lcv[li];
        int in = (li + 1) & 1, outi = li & 1;
        agg_kernel<<<(NN + 7) / 8, 256>>>(curF, aq1, aq2, rsA,
                                          csrp + (size_t)es * NN * DCAP, degp + es * NN);
        sage_mma<<<148, 512, SMEMSZ>>>(
            aq1, aq2, rsA,
            hq1 + (size_t)in * bufsz, hq2 + (size_t)in * bufsz, rsH + in * NN,
            wqp + (size_t)cv * 4 * HH * HH, csbp + cv * 256, bl[cv],
            bufA, hq1 + (size_t)outi * bufsz, hq2 + (size_t)outi * bufsz, rsH + outi * NN,
            Lnm[li], li == 6 ? 0 : 1);
        curF = bufA;
    }

    pool_kernel<<<(NN + PCH - 1) / PCH, 128>>>(bufA, batch, poolp, degp);
    mlp_kernel<<<1, 256>>>(poolp, l0W, l0b, l1W, l1b, headW, headb, (float*)d_out);
}

// round 16
// speedup vs baseline: 1.8557x; 1.8557x over previous
#include <cuda_runtime.h>
#include <cuda_fp16.h>
#include <math.h>
#include <stdint.h>

#define NN 50000
#define EE 600000
#define HH 128
#define GG 64
#define PCH 64
#define DCAP 64
#define NTILES 391   // ceil(50000/128)

// ---- static device scratch ----
__device__ float g_bufA[(size_t)NN * HH];
__device__ float g_pool[GG * HH];
__device__ int   g_deg[3 * NN];                 // zeroed at load; re-zeroed by pool_kernel
__device__ int   g_csr[(size_t)3 * NN * DCAP];
__device__ __half g_hH[2][(size_t)NN * HH];     // fp16 hi (ping-pong)
__device__ __half g_hL[2][(size_t)NN * HH];     // fp16 lo residual
__device__ __half g_aggH[(size_t)NN * HH];
__device__ __half g_aggL[(size_t)NN * HH];
// weights fp16 single: [conv 5][phase 2][n=128][k=128]
__device__ __half g_wtb[5 * 2 * HH * HH];

// ================= helpers =================
__device__ __forceinline__ uint32_t s2u(const void* p) {
    uint32_t a;
    asm("{ .reg .u64 t; cvta.to.shared.u64 t, %1; cvt.u32.u64 %0, t; }" : "=r"(a) : "l"(p));
    return a;
}
__device__ __forceinline__ void cpa16(uint32_t d, const void* s, uint32_t ssz) {
    asm volatile("cp.async.cg.shared.global [%0], [%1], 16, %2;"
                 :: "r"(d), "l"(s), "r"(ssz) : "memory");
}
__device__ __forceinline__ void cpa_commit() {
    asm volatile("cp.async.commit_group;" ::: "memory");
}
template <int N>
__device__ __forceinline__ void cpa_wait() {
    asm volatile("cp.async.wait_group %0;" :: "n"(N) : "memory");
}
#define LDSM4(r0, r1, r2, r3, a) \
    asm volatile("ldmatrix.sync.aligned.m8n8.x4.shared.b16 {%0,%1,%2,%3}, [%4];" \
                 : "=r"(r0), "=r"(r1), "=r"(r2), "=r"(r3) : "r"(a))
#define MMA_FP16(c, a, b) \
    asm volatile("mma.sync.aligned.m16n8k16.row.col.f32.f16.f16.f32 " \
                 "{%0,%1,%2,%3},{%4,%5,%6,%7},{%8,%9},{%0,%1,%2,%3};" \
                 : "+f"((c)[0]), "+f"((c)[1]), "+f"((c)[2]), "+f"((c)[3]) \
                 : "r"((a)[0]), "r"((a)[1]), "r"((a)[2]), "r"((a)[3]), \
                   "r"((b)[0]), "r"((b)[1]))

// smem: B 2x32KB @0, A 3 bufs x 32KB @65536, ssred @163840 (2KB)
#define SM_B 0
#define SM_A 65536
#define SM_SS 163840
#define SMEMSZ 165888

__device__ __forceinline__ void h2pair(float v0, float v1, __half2& hv, __half2& lv) {
    hv.x = __float2half(v0);
    hv.y = __float2half(v1);
    lv.x = __float2half(v0 - __half2float(hv.x));
    lv.y = __float2half(v1 - __half2float(hv.y));
}

// ---------------- fused setup: bucketed CSR + x->fp16 hi/lo + weight prep + pool zero
struct WPtrs { const float* Wl[5]; const float* Wr[5]; };
#define CB 7032
#define XB 6250
#define WB 320
#define PB 32
__global__ __launch_bounds__(256) void setup_kernel(const int* __restrict__ e0,
                                                    const int* __restrict__ e1,
                                                    const int* __restrict__ e2,
                                                    WPtrs wp,
                                                    const float* __restrict__ x,
                                                    __half* __restrict__ oh,
                                                    __half* __restrict__ ol,
                                                    __half* __restrict__ wtb,
                                                    int* __restrict__ deg,
                                                    int* __restrict__ csr,
                                                    float* __restrict__ poolp) {
    int b = blockIdx.x, tid = threadIdx.x;
    if (b < CB) {
        int t = b * 256 + tid;
        if (t < 3 * EE) {
            int s = t / EE, i = t - s * EE;
            const int* e = (s == 0) ? e0 : ((s == 1) ? e1 : e2);
            int dst = e[EE + i];
            int p = atomicAdd(&deg[s * NN + dst], 1);
            if (p < DCAP) csr[((size_t)s * NN + dst) * DCAP + p] = e[i];
        }
    } else if (b < CB + XB) {
        int i = (b - CB) * 256 + tid;
        float4 v = ((const float4*)x)[i];
        __half2 h01, h23, l01, l23;
        h2pair(v.x, v.y, h01, l01);
        h2pair(v.z, v.w, h23, l23);
        ((__half2*)oh)[i * 2] = h01; ((__half2*)oh)[i * 2 + 1] = h23;
        ((__half2*)ol)[i * 2] = l01; ((__half2*)ol)[i * 2 + 1] = l23;
    } else if (b < CB + XB + WB) {
        int idx = (b - CB - XB) * 256 + tid;
        int cv = idx >> 14, rem = idx & 16383;
        int n = rem >> 7, k = rem & 127;
        __half* base = wtb + (size_t)cv * 2 * HH * HH;
        base[n * HH + k] = __float2half(wp.Wl[cv][k * HH + n]);
        base[HH * HH + n * HH + k] = __float2half(wp.Wr[cv][k * HH + n]);
    } else {
        int g = (b - CB - XB - WB) * 256 + tid;
        if (g < GG * HH) poolp[g] = 0.f;
    }
}

// ---------------- mean aggregation: fp32 gather + fp16 hi/lo epilogue ----------------
__global__ __launch_bounds__(256) void agg_kernel(const float* __restrict__ fsrc,
                                                  __half* __restrict__ aggH,
                                                  __half* __restrict__ aggL,
                                                  const int* __restrict__ csr,
                                                  const int* __restrict__ deg) {
    int node = blockIdx.x * 8 + (threadIdx.x >> 5);
    if (node >= NN) return;
    int lane = threadIdx.x & 31;
    int co = lane * 4;
    int d = deg[node];
    int dr = min(d, DCAP);
    const int* nb = csr + (size_t)node * DCAP;
    float4 acc = make_float4(0.f, 0.f, 0.f, 0.f);

    int p = 0;
    for (; p + 4 <= dr; p += 4) {
        int4 iv = *(const int4*)(nb + p);
        float4 v0 = *(const float4*)(fsrc + (size_t)iv.x * HH + co);
        float4 v1 = *(const float4*)(fsrc + (size_t)iv.y * HH + co);
        float4 v2 = *(const float4*)(fsrc + (size_t)iv.z * HH + co);
        float4 v3 = *(const float4*)(fsrc + (size_t)iv.w * HH + co);
        acc.x += v0.x + v1.x + v2.x + v3.x;
        acc.y += v0.y + v1.y + v2.y + v3.y;
        acc.z += v0.z + v1.z + v2.z + v3.z;
        acc.w += v0.w + v1.w + v2.w + v3.w;
    }
    for (; p < dr; ++p) {
        float4 v0 = *(const float4*)(fsrc + (size_t)nb[p] * HH + co);
        acc.x += v0.x; acc.y += v0.y; acc.z += v0.z; acc.w += v0.w;
    }
    float inv = 1.f / fmaxf((float)d, 1.f);
    acc.x *= inv; acc.y *= inv; acc.z *= inv; acc.w *= inv;

    __half2 h01, h23, l01, l23;
    h2pair(acc.x, acc.y, h01, l01);
    h2pair(acc.z, acc.w, h23, l23);
    uint2 ho, lo;
    ho.x = *(uint32_t*)&h01; ho.y = *(uint32_t*)&h23;
    lo.x = *(uint32_t*)&l01; lo.y = *(uint32_t*)&l23;
    *(uint2*)(aggH + (size_t)node * HH + co) = ho;
    *(uint2*)(aggL + (size_t)node * HH + co) = lo;
}

// ---------------- persistent fp16 A-split tensor-core SAGE GEMM, 512 threads ----------------
// 2 products per k-step: Ah*B + Al*B (A 22-bit effective, B single fp16).
__global__ __launch_bounds__(512) void sage_mma(const __half* __restrict__ aggH,
                                                const __half* __restrict__ aggL,
                                                const __half* __restrict__ hinH,
                                                const __half* __restrict__ hinL,
                                                const __half* __restrict__ wb,
                                                const float* __restrict__ bias,
                                                float* __restrict__ outF,
                                                __half* __restrict__ outH,
                                                __half* __restrict__ outL,
                                                int doNorm, int writeB) {
    extern __shared__ char smem[];
    const uint32_t sb = s2u(smem);
    const int tid = threadIdx.x;
    const int wid = tid >> 5, lane = tid & 31;
    const int wm = wid >> 2, wn = wid & 3;
    const int bid = blockIdx.x;
    const int nch = 4 * ((NTILES - bid + 147) / 148);

    // B load: 2 matrices x 32KB (fp16, 256B rows), swizzled
#pragma unroll
    for (int i = 0; i < 8; i++) {
        int idx = tid + i * 512;          // 0..4095 16B units
        int mat = idx >> 11, u = idx & 2047;
        int n = u >> 4, kunit = u & 15;
        uint32_t off = (uint32_t)(n * 256 + kunit * 16);
        uint32_t sw = off ^ ((off >> 4) & 0x70);
        cpa16(sb + SM_B + mat * 32768 + sw, wb + (size_t)idx * 8, 16u);
    }
    auto issueA = [&](int ch) {
        int tile = bid + (ch >> 2) * 148;
        int c = ch & 3, buf = ch % 3;
        int m0 = tile * 128;
        const __half* sH = (c < 2) ? aggH : hinH;
        const __half* sL = (c < 2) ? aggL : hinL;
        int koff = (c & 1) * 64;
#pragma unroll
        for (int i = 0; i < 2; i++) {
            int idx = tid + i * 512;
            int r = idx >> 3, ku = idx & 7;
            int gm = m0 + r;
            uint32_t off = (uint32_t)(r * 128 + ku * 16);
            uint32_t sw = off ^ ((off >> 3) & 0x70);
            uint32_t ssz = (gm < NN) ? 16u : 0u;
            int gmc = (gm < NN) ? gm : 0;
            cpa16(sb + SM_A + buf * 32768 + sw,         sH + (size_t)gmc * HH + koff + ku * 8, ssz);
            cpa16(sb + SM_A + buf * 32768 + 16384 + sw, sL + (size_t)gmc * HH + koff + ku * 8, ssz);
        }
    };
    issueA(0); cpa_commit();
    issueA(1); cpa_commit();

    float acc[2][4][4];
#pragma unroll
    for (int mf = 0; mf < 2; mf++)
#pragma unroll
        for (int nf = 0; nf < 4; nf++)
#pragma unroll
            for (int q = 0; q < 4; q++) acc[mf][nf][q] = 0.f;

    float* ssred = (float*)(smem + SM_SS);
    float bc[4][2];
#pragma unroll
    for (int nf = 0; nf < 4; nf++) {
        int col = wn * 32 + nf * 8 + (lane & 3) * 2;
        bc[nf][0] = __ldg(bias + col);
        bc[nf][1] = __ldg(bias + col + 1);
    }

    const uint32_t rAl = (uint32_t)(wm * 32 + (lane & 15));
    const uint32_t kAl = (uint32_t)((lane >> 4) * 16);
    const uint32_t nBl = (uint32_t)(wn * 32 + ((lane >> 4) << 3) + (lane & 7));
    const uint32_t kBl = (uint32_t)(((lane >> 3) & 1) * 16);

    for (int ch = 0; ch < nch; ch++) {
        if (ch + 2 < nch) cpa_wait<1>(); else cpa_wait<0>();
        __syncthreads();
        if (ch + 2 < nch) { issueA(ch + 2); cpa_commit(); }

        const int buf = ch % 3, c = ch & 3, ph = c >> 1;
        const uint32_t Ah = sb + SM_A + buf * 32768;
        const uint32_t Al = Ah + 16384;
        const uint32_t Bh = sb + SM_B + ph * 32768;
        const uint32_t kbB0 = (uint32_t)((c & 1) * 128);
#pragma unroll
        for (int kc = 0; kc < 4; kc++) {
            uint32_t kbA = kc * 32 + kAl;
            uint32_t kbB = kbB0 + kc * 32 + kBl;
            uint32_t ah[2][4], al[2][4];
#pragma unroll
            for (int mf = 0; mf < 2; mf++) {
                uint32_t off = (rAl + mf * 16) * 128 + kbA;
                uint32_t sw = off ^ ((off >> 3) & 0x70);
                LDSM4(ah[mf][0], ah[mf][1], ah[mf][2], ah[mf][3], Ah + sw);
                LDSM4(al[mf][0], al[mf][1], al[mf][2], al[mf][3], Al + sw);
            }
            uint32_t bh[4][2];
#pragma unroll
            for (int np = 0; np < 2; np++) {
                uint32_t off = (nBl + np * 16) * 256 + kbB;
                uint32_t sw = off ^ ((off >> 4) & 0x70);
                uint32_t r0, r1, r2, r3;
                LDSM4(r0, r1, r2, r3, Bh + sw);
                bh[2 * np][0] = r0; bh[2 * np][1] = r1;
                bh[2 * np + 1][0] = r2; bh[2 * np + 1][1] = r3;
            }
#pragma unroll
            for (int mf = 0; mf < 2; mf++)
#pragma unroll
                for (int nf = 0; nf < 4; nf++) {
                    MMA_FP16(acc[mf][nf], ah[mf], bh[nf]);
                    MMA_FP16(acc[mf][nf], al[mf], bh[nf]);
                }
        }

        if ((ch & 3) == 3) {
            // ---------------- epilogue for this tile ----------------
            int m0 = (bid + (ch >> 2) * 148) * 128;
#pragma unroll
            for (int mf = 0; mf < 2; mf++)
#pragma unroll
                for (int nf = 0; nf < 4; nf++) {
                    acc[mf][nf][0] += bc[nf][0];
                    acc[mf][nf][1] += bc[nf][1];
                    acc[mf][nf][2] += bc[nf][0];
                    acc[mf][nf][3] += bc[nf][1];
                }
            float scale[2][2];
            if (doNorm) {
#pragma unroll
                for (int mf = 0; mf < 2; mf++) {
                    float s0 = 0.f, s1 = 0.f;
#pragma unroll
                    for (int nf = 0; nf < 4; nf++) {
                        s0 += acc[mf][nf][0] * acc[mf][nf][0] + acc[mf][nf][1] * acc[mf][nf][1];
                        s1 += acc[mf][nf][2] * acc[mf][nf][2] + acc[mf][nf][3] * acc[mf][nf][3];
                    }
                    s0 += __shfl_xor_sync(0xffffffffu, s0, 1);
                    s0 += __shfl_xor_sync(0xffffffffu, s0, 2);
                    s1 += __shfl_xor_sync(0xffffffffu, s1, 1);
                    s1 += __shfl_xor_sync(0xffffffffu, s1, 2);
                    if ((lane & 3) == 0) {
                        int r = wm * 32 + mf * 16 + (lane >> 2);
                        ssred[r * 4 + wn] = s0;
                        ssred[(r + 8) * 4 + wn] = s1;
                    }
                }
                __syncthreads();
#pragma unroll
                for (int mf = 0; mf < 2; mf++) {
                    int r = wm * 32 + mf * 16 + (lane >> 2);
                    float t0 = ssred[r * 4] + ssred[r * 4 + 1] + ssred[r * 4 + 2] + ssred[r * 4 + 3];
                    int r1 = r + 8;
                    float t1 = ssred[r1 * 4] + ssred[r1 * 4 + 1] + ssred[r1 * 4 + 2] + ssred[r1 * 4 + 3];
                    scale[mf][0] = 1.f / fmaxf(sqrtf(t0), 1e-12f);
                    scale[mf][1] = 1.f / fmaxf(sqrtf(t1), 1e-12f);
                }
            } else {
#pragma unroll
                for (int mf = 0; mf < 2; mf++) { scale[mf][0] = 1.f; scale[mf][1] = 1.f; }
            }
#pragma unroll
            for (int mf = 0; mf < 2; mf++)
#pragma unroll
                for (int hh = 0; hh < 2; hh++) {
                    int r = m0 + wm * 32 + mf * 16 + (lane >> 2) + hh * 8;
                    if (r < NN) {
#pragma unroll
                        for (int nf = 0; nf < 4; nf++) {
                            int col = wn * 32 + nf * 8 + (lane & 3) * 2;
                            float v0 = acc[mf][nf][2 * hh] * scale[mf][hh];
                            float v1 = acc[mf][nf][2 * hh + 1] * scale[mf][hh];
                            *(float2*)(outF + (size_t)r * HH + col) = make_float2(v0, v1);
                            if (writeB) {
                                __half2 hv, lv;
                                h2pair(v0, v1, hv, lv);
                                *(__half2*)(outH + (size_t)r * HH + col) = hv;
                                *(__half2*)(outL + (size_t)r * HH + col) = lv;
                            }
                        }
                    }
                }
#pragma unroll
            for (int mf = 0; mf < 2; mf++)
#pragma unroll
                for (int nf = 0; nf < 4; nf++)
#pragma unroll
                    for (int q = 0; q < 4; q++) acc[mf][nf][q] = 0.f;
        }
    }
}

// ---------------- global_add_pool (+ re-zero deg for next replay) ----------------
__global__ __launch_bounds__(128) void pool_kernel(const float* __restrict__ h,
                                                   const int* __restrict__ batch,
                                                   float* __restrict__ pool,
                                                   int* __restrict__ deg) {
    int gtid = blockIdx.x * 128 + threadIdx.x;
    for (int i = gtid; i < 3 * NN; i += gridDim.x * 128) deg[i] = 0;
    int c = threadIdx.x;
    int start = blockIdx.x * PCH;
    if (start >= NN) return;
    int end = min(start + PCH, NN);
    int cur = batch[start];
    float acc = 0.f;
    for (int i = start; i < end; ++i) {
        int b = batch[i];
        if (b != cur) { atomicAdd(&pool[cur * HH + c], acc); acc = 0.f; cur = b; }
        acc += h[(size_t)i * HH + c];
    }
    atomicAdd(&pool[cur * HH + c], acc);
}

// ---------------- MLP head ----------------
__global__ __launch_bounds__(256) void mlp_kernel(const float* __restrict__ pool,
                                                  const float* __restrict__ W0, const float* __restrict__ b0,
                                                  const float* __restrict__ W1, const float* __restrict__ b1,
                                                  const float* __restrict__ hW, const float* __restrict__ hb,
                                                  float* __restrict__ out) {
    __shared__ float Gs[GG * HH];
    int tid = threadIdx.x;
    for (int i = tid; i < GG * HH / 4; i += 256)
        ((float4*)Gs)[i] = ((const float4*)pool)[i];
    __syncthreads();
    int c = tid & 127;
    int rb = tid >> 7;
    float s[32];
#pragma unroll
    for (int j = 0; j < 32; j++) s[j] = b0[c];
    for (int k = 0; k < HH; k++) {
        float w = __ldg(W0 + k * HH + c);
#pragma unroll
        for (int j = 0; j < 32; j++) s[j] = fmaf(Gs[(rb + 2 * j) * HH + k], w, s[j]);
    }
    __syncthreads();
#pragma unroll
    for (int j = 0; j < 32; j++) Gs[(rb + 2 * j) * HH + c] = fmaxf(s[j], 0.f);
    __syncthreads();
#pragma unroll
    for (int j = 0; j < 32; j++) s[j] = b1[c];
    for (int k = 0; k < HH; k++) {
        float w = __ldg(W1 + k * HH + c);
#pragma unroll
        for (int j = 0; j < 32; j++) s[j] = fmaf(Gs[(rb + 2 * j) * HH + k], w, s[j]);
    }
    __syncthreads();
#pragma unroll
    for (int j = 0; j < 32; j++) Gs[(rb + 2 * j) * HH + c] = fmaxf(s[j], 0.f);
    __syncthreads();
    if (tid < GG) {
        float acc = hb[0];
        for (int k = 0; k < HH; k++) acc = fmaf(Gs[tid * HH + k], hW[k], acc);
        out[tid] = acc;
    }
}

// ---------------- driver ----------------
extern "C" void kernel_launch(void* const* d_in, const int* in_sizes, int n_in,
                              void* d_out, int out_size) {
    const float* x     = (const float*)d_in[0];
    const int*   eic   = (const int*)d_in[1];
    const int*   eid   = (const int*)d_in[2];
    const int*   eit   = (const int*)d_in[3];
    const int*   batch = (const int*)d_in[4];
    WPtrs wp;
    const float* bl[5];
    for (int i = 0; i < 5; i++) {
        wp.Wl[i] = (const float*)d_in[5 + 3 * i];
        bl[i]    = (const float*)d_in[6 + 3 * i];
        wp.Wr[i] = (const float*)d_in[7 + 3 * i];
    }
    const float* l0W   = (const float*)d_in[20];
    const float* l0b   = (const float*)d_in[21];
    const float* l1W   = (const float*)d_in[22];
    const float* l1b   = (const float*)d_in[23];
    const float* headW = (const float*)d_in[24];
    const float* headb = (const float*)d_in[25];

    void* p;
    cudaGetSymbolAddress(&p, g_bufA); float* bufA = (float*)p;
    cudaGetSymbolAddress(&p, g_pool); float* poolp = (float*)p;
    cudaGetSymbolAddress(&p, g_deg);  int* degp = (int*)p;
    cudaGetSymbolAddress(&p, g_csr);  int* csrp = (int*)p;
    cudaGetSymbolAddress(&p, g_hH);   __half* hH = (__half*)p;
    cudaGetSymbolAddress(&p, g_hL);   __half* hL = (__half*)p;
    cudaGetSymbolAddress(&p, g_aggH); __half* aggH = (__half*)p;
    cudaGetSymbolAddress(&p, g_aggL); __half* aggL = (__half*)p;
    cudaGetSymbolAddress(&p, g_wtb);  __half* wtb = (__half*)p;

    cudaFuncSetAttribute(sage_mma, cudaFuncAttributeMaxDynamicSharedMemorySize, SMEMSZ);

    size_t bufsz = (size_t)NN * HH;
    setup_kernel<<<CB + XB + WB + PB, 256>>>(eid, eic, eit, wp, x,
                                             hH + bufsz, hL + bufsz, wtb, degp, csrp, poolp);

    const int Les[7] = {0, 1, 1, 2, 0, 1, 1};
    const int Lcv[7] = {0, 1, 1, 2, 3, 4, 4};
    const int Lnm[7] = {1, 1, 1, 0, 1, 1, 1};

    const float* curF = x;
    for (int li = 0; li < 7; ++li) {
        int es = Les[li], cv = Lcv[li];
        int in = (li + 1) & 1, outi = li & 1;
        agg_kernel<<<(NN + 7) / 8, 256>>>(curF, aggH, aggL,
                                          csrp + (size_t)es * NN * DCAP, degp + es * NN);
        sage_mma<<<148, 512, SMEMSZ>>>(
            aggH, aggL, hH + (size_t)in * bufsz, hL + (size_t)in * bufsz,
            wtb + (size_t)cv * 2 * HH * HH, bl[cv],
            bufA, hH + (size_t)outi * bufsz, hL + (size_t)outi * bufsz,
            Lnm[li], li == 6 ? 0 : 1);
        curF = bufA;
    }

    pool_kernel<<<(NN + PCH - 1) / PCH, 128>>>(bufA, batch, poolp, degp);
    mlp_kernel<<<1, 256>>>(poolp, l0W, l0b, l1W, l1b, headW, headb, (float*)d_out);
}

// round 17
// speedup vs baseline: 1.9810x; 1.0675x over previous
#include <cuda_runtime.h>
#include <cuda_fp16.h>
#include <math.h>
#include <stdint.h>

#define NN 50000
#define EE 600000
#define HH 128
#define GG 64
#define PCH 64
#define DCAP 64
#define NTILES 391   // ceil(50000/128)

// ---- static device scratch ----
__device__ float g_bufA[(size_t)NN * HH];
__device__ float g_pool[GG * HH];
__device__ int   g_deg[3 * NN];                 // zeroed at load; re-zeroed by pool_kernel
__device__ int   g_csr[(size_t)3 * NN * DCAP];
__device__ __half g_hH[2][(size_t)NN * HH];     // fp16 hi (ping-pong)
__device__ __half g_hL[2][(size_t)NN * HH];     // fp16 lo residual
__device__ __half g_aggH[(size_t)NN * HH];
__device__ __half g_aggL[(size_t)NN * HH];
// weights fp16 single: [conv 5][phase 2][n=128][k=128]
__device__ __half g_wtb[5 * 2 * HH * HH];

// ================= helpers =================
__device__ __forceinline__ uint32_t s2u(const void* p) {
    uint32_t a;
    asm("{ .reg .u64 t; cvta.to.shared.u64 t, %1; cvt.u32.u64 %0, t; }" : "=r"(a) : "l"(p));
    return a;
}
__device__ __forceinline__ void cpa16(uint32_t d, const void* s, uint32_t ssz) {
    asm volatile("cp.async.cg.shared.global [%0], [%1], 16, %2;"
                 :: "r"(d), "l"(s), "r"(ssz) : "memory");
}
__device__ __forceinline__ void cpa_commit() {
    asm volatile("cp.async.commit_group;" ::: "memory");
}
template <int N>
__device__ __forceinline__ void cpa_wait() {
    asm volatile("cp.async.wait_group %0;" :: "n"(N) : "memory");
}
#define LDSM4(r0, r1, r2, r3, a) \
    asm volatile("ldmatrix.sync.aligned.m8n8.x4.shared.b16 {%0,%1,%2,%3}, [%4];" \
                 : "=r"(r0), "=r"(r1), "=r"(r2), "=r"(r3) : "r"(a))
#define MMA_FP16(c, a, b) \
    asm volatile("mma.sync.aligned.m16n8k16.row.col.f32.f16.f16.f32 " \
                 "{%0,%1,%2,%3},{%4,%5,%6,%7},{%8,%9},{%0,%1,%2,%3};" \
                 : "+f"((c)[0]), "+f"((c)[1]), "+f"((c)[2]), "+f"((c)[3]) \
                 : "r"((a)[0]), "r"((a)[1]), "r"((a)[2]), "r"((a)[3]), \
                   "r"((b)[0]), "r"((b)[1]))

// smem: B 2x32KB @0, A 3 bufs x 32KB @65536, ssred @163840 (2KB)
#define SM_B 0
#define SM_A 65536
#define SM_SS 163840
#define SMEMSZ 165888

__device__ __forceinline__ void h2pair(float v0, float v1, __half2& hv, __half2& lv) {
    hv.x = __float2half(v0);
    hv.y = __float2half(v1);
    lv.x = __float2half(v0 - __half2float(hv.x));
    lv.y = __float2half(v1 - __half2float(hv.y));
}

// ---------------- fused setup: bucketed CSR + x->fp16 hi/lo + weight prep + pool zero
struct WPtrs { const float* Wl[5]; const float* Wr[5]; };
#define CB 7032
#define XB 6250
#define WB 320
#define PB 32
__global__ __launch_bounds__(256) void setup_kernel(const int* __restrict__ e0,
                                                    const int* __restrict__ e1,
                                                    const int* __restrict__ e2,
                                                    WPtrs wp,
                                                    const float* __restrict__ x,
                                                    __half* __restrict__ oh,
                                                    __half* __restrict__ ol,
                                                    __half* __restrict__ wtb,
                                                    int* __restrict__ deg,
                                                    int* __restrict__ csr,
                                                    float* __restrict__ poolp) {
    int b = blockIdx.x, tid = threadIdx.x;
    if (b < CB) {
        int t = b * 256 + tid;
        if (t < 3 * EE) {
            int s = t / EE, i = t - s * EE;
            const int* e = (s == 0) ? e0 : ((s == 1) ? e1 : e2);
            int dst = e[EE + i];
            int p = atomicAdd(&deg[s * NN + dst], 1);
            if (p < DCAP) csr[((size_t)s * NN + dst) * DCAP + p] = e[i];
        }
    } else if (b < CB + XB) {
        int i = (b - CB) * 256 + tid;
        float4 v = ((const float4*)x)[i];
        __half2 h01, h23, l01, l23;
        h2pair(v.x, v.y, h01, l01);
        h2pair(v.z, v.w, h23, l23);
        ((__half2*)oh)[i * 2] = h01; ((__half2*)oh)[i * 2 + 1] = h23;
        ((__half2*)ol)[i * 2] = l01; ((__half2*)ol)[i * 2 + 1] = l23;
    } else if (b < CB + XB + WB) {
        int idx = (b - CB - XB) * 256 + tid;
        int cv = idx >> 14, rem = idx & 16383;
        int n = rem >> 7, k = rem & 127;
        __half* base = wtb + (size_t)cv * 2 * HH * HH;
        base[n * HH + k] = __float2half(wp.Wl[cv][k * HH + n]);
        base[HH * HH + n * HH + k] = __float2half(wp.Wr[cv][k * HH + n]);
    } else {
        int g = (b - CB - XB - WB) * 256 + tid;
        if (g < GG * HH) poolp[g] = 0.f;
    }
}

// ---------------- mean aggregation: fp16-hi gather, fp32 accumulate ----------------
__global__ __launch_bounds__(256) void agg_kernel(const __half* __restrict__ hsrc,
                                                  __half* __restrict__ aggH,
                                                  __half* __restrict__ aggL,
                                                  const int* __restrict__ csr,
                                                  const int* __restrict__ deg) {
    int node = blockIdx.x * 8 + (threadIdx.x >> 5);
    if (node >= NN) return;
    int lane = threadIdx.x & 31;
    int co = lane * 4;
    int d = deg[node];
    int dr = min(d, DCAP);
    const int* nb = csr + (size_t)node * DCAP;
    float4 acc = make_float4(0.f, 0.f, 0.f, 0.f);

    auto addv = [&](uint2 v) {
        float2 f0 = __half22float2(*(__half2*)&v.x);
        float2 f1 = __half22float2(*(__half2*)&v.y);
        acc.x += f0.x; acc.y += f0.y; acc.z += f1.x; acc.w += f1.y;
    };

    int p = 0;
    for (; p + 4 <= dr; p += 4) {
        int4 iv = *(const int4*)(nb + p);
        uint2 v0 = *(const uint2*)(hsrc + (size_t)iv.x * HH + co);
        uint2 v1 = *(const uint2*)(hsrc + (size_t)iv.y * HH + co);
        uint2 v2 = *(const uint2*)(hsrc + (size_t)iv.z * HH + co);
        uint2 v3 = *(const uint2*)(hsrc + (size_t)iv.w * HH + co);
        addv(v0); addv(v1); addv(v2); addv(v3);
    }
    for (; p < dr; ++p) {
        uint2 v0 = *(const uint2*)(hsrc + (size_t)nb[p] * HH + co);
        addv(v0);
    }
    float inv = 1.f / fmaxf((float)d, 1.f);
    acc.x *= inv; acc.y *= inv; acc.z *= inv; acc.w *= inv;

    __half2 h01, h23, l01, l23;
    h2pair(acc.x, acc.y, h01, l01);
    h2pair(acc.z, acc.w, h23, l23);
    uint2 ho, lo;
    ho.x = *(uint32_t*)&h01; ho.y = *(uint32_t*)&h23;
    lo.x = *(uint32_t*)&l01; lo.y = *(uint32_t*)&l23;
    *(uint2*)(aggH + (size_t)node * HH + co) = ho;
    *(uint2*)(aggL + (size_t)node * HH + co) = lo;
}

// ---------------- persistent fp16 A-split tensor-core SAGE GEMM, 512 threads ----------------
// 2 products per k-step: Ah*B + Al*B. fp32 out written only on the last layer.
__global__ __launch_bounds__(512) void sage_mma(const __half* __restrict__ aggH,
                                                const __half* __restrict__ aggL,
                                                const __half* __restrict__ hinH,
                                                const __half* __restrict__ hinL,
                                                const __half* __restrict__ wb,
                                                const float* __restrict__ bias,
                                                float* __restrict__ outF,
                                                __half* __restrict__ outH,
                                                __half* __restrict__ outL,
                                                int doNorm, int writeF, int writeB) {
    extern __shared__ char smem[];
    const uint32_t sb = s2u(smem);
    const int tid = threadIdx.x;
    const int wid = tid >> 5, lane = tid & 31;
    const int wm = wid >> 2, wn = wid & 3;
    const int bid = blockIdx.x;
    const int nch = 4 * ((NTILES - bid + 147) / 148);

    // B load: 2 matrices x 32KB (fp16, 256B rows), swizzled
#pragma unroll
    for (int i = 0; i < 8; i++) {
        int idx = tid + i * 512;
        int mat = idx >> 11, u = idx & 2047;
        int n = u >> 4, kunit = u & 15;
        uint32_t off = (uint32_t)(n * 256 + kunit * 16);
        uint32_t sw = off ^ ((off >> 4) & 0x70);
        cpa16(sb + SM_B + mat * 32768 + sw, wb + (size_t)idx * 8, 16u);
    }
    auto issueA = [&](int ch) {
        int tile = bid + (ch >> 2) * 148;
        int c = ch & 3, buf = ch % 3;
        int m0 = tile * 128;
        const __half* sH = (c < 2) ? aggH : hinH;
        const __half* sL = (c < 2) ? aggL : hinL;
        int koff = (c & 1) * 64;
#pragma unroll
        for (int i = 0; i < 2; i++) {
            int idx = tid + i * 512;
            int r = idx >> 3, ku = idx & 7;
            int gm = m0 + r;
            uint32_t off = (uint32_t)(r * 128 + ku * 16);
            uint32_t sw = off ^ ((off >> 3) & 0x70);
            uint32_t ssz = (gm < NN) ? 16u : 0u;
            int gmc = (gm < NN) ? gm : 0;
            cpa16(sb + SM_A + buf * 32768 + sw,         sH + (size_t)gmc * HH + koff + ku * 8, ssz);
            cpa16(sb + SM_A + buf * 32768 + 16384 + sw, sL + (size_t)gmc * HH + koff + ku * 8, ssz);
        }
    };
    issueA(0); cpa_commit();
    issueA(1); cpa_commit();

    float acc[2][4][4];
#pragma unroll
    for (int mf = 0; mf < 2; mf++)
#pragma unroll
        for (int nf = 0; nf < 4; nf++)
#pragma unroll
            for (int q = 0; q < 4; q++) acc[mf][nf][q] = 0.f;

    float* ssred = (float*)(smem + SM_SS);
    float bc[4][2];
#pragma unroll
    for (int nf = 0; nf < 4; nf++) {
        int col = wn * 32 + nf * 8 + (lane & 3) * 2;
        bc[nf][0] = __ldg(bias + col);
        bc[nf][1] = __ldg(bias + col + 1);
    }

    const uint32_t rAl = (uint32_t)(wm * 32 + (lane & 15));
    const uint32_t kAl = (uint32_t)((lane >> 4) * 16);
    const uint32_t nBl = (uint32_t)(wn * 32 + ((lane >> 4) << 3) + (lane & 7));
    const uint32_t kBl = (uint32_t)(((lane >> 3) & 1) * 16);

    for (int ch = 0; ch < nch; ch++) {
        if (ch + 2 < nch) cpa_wait<1>(); else cpa_wait<0>();
        __syncthreads();
        if (ch + 2 < nch) { issueA(ch + 2); cpa_commit(); }

        const int buf = ch % 3, c = ch & 3, ph = c >> 1;
        const uint32_t Ah = sb + SM_A + buf * 32768;
        const uint32_t Al = Ah + 16384;
        const uint32_t Bh = sb + SM_B + ph * 32768;
        const uint32_t kbB0 = (uint32_t)((c & 1) * 128);
#pragma unroll
        for (int kc = 0; kc < 4; kc++) {
            uint32_t kbA = kc * 32 + kAl;
            uint32_t kbB = kbB0 + kc * 32 + kBl;
            uint32_t ah[2][4], al[2][4];
#pragma unroll
            for (int mf = 0; mf < 2; mf++) {
                uint32_t off = (rAl + mf * 16) * 128 + kbA;
                uint32_t sw = off ^ ((off >> 3) & 0x70);
                LDSM4(ah[mf][0], ah[mf][1], ah[mf][2], ah[mf][3], Ah + sw);
                LDSM4(al[mf][0], al[mf][1], al[mf][2], al[mf][3], Al + sw);
            }
            uint32_t bh[4][2];
#pragma unroll
            for (int np = 0; np < 2; np++) {
                uint32_t off = (nBl + np * 16) * 256 + kbB;
                uint32_t sw = off ^ ((off >> 4) & 0x70);
                uint32_t r0, r1, r2, r3;
                LDSM4(r0, r1, r2, r3, Bh + sw);
                bh[2 * np][0] = r0; bh[2 * np][1] = r1;
                bh[2 * np + 1][0] = r2; bh[2 * np + 1][1] = r3;
            }
#pragma unroll
            for (int mf = 0; mf < 2; mf++)
#pragma unroll
                for (int nf = 0; nf < 4; nf++) {
                    MMA_FP16(acc[mf][nf], ah[mf], bh[nf]);
                    MMA_FP16(acc[mf][nf], al[mf], bh[nf]);
                }
        }

        if ((ch & 3) == 3) {
            // ---------------- epilogue for this tile ----------------
            int m0 = (bid + (ch >> 2) * 148) * 128;
#pragma unroll
            for (int mf = 0; mf < 2; mf++)
#pragma unroll
                for (int nf = 0; nf < 4; nf++) {
                    acc[mf][nf][0] += bc[nf][0];
                    acc[mf][nf][1] += bc[nf][1];
                    acc[mf][nf][2] += bc[nf][0];
                    acc[mf][nf][3] += bc[nf][1];
                }
            float scale[2][2];
            if (doNorm) {
#pragma unroll
                for (int mf = 0; mf < 2; mf++) {
                    float s0 = 0.f, s1 = 0.f;
#pragma unroll
                    for (int nf = 0; nf < 4; nf++) {
                        s0 += acc[mf][nf][0] * acc[mf][nf][0] + acc[mf][nf][1] * acc[mf][nf][1];
                        s1 += acc[mf][nf][2] * acc[mf][nf][2] + acc[mf][nf][3] * acc[mf][nf][3];
                    }
                    s0 += __shfl_xor_sync(0xffffffffu, s0, 1);
                    s0 += __shfl_xor_sync(0xffffffffu, s0, 2);
                    s1 += __shfl_xor_sync(0xffffffffu, s1, 1);
                    s1 += __shfl_xor_sync(0xffffffffu, s1, 2);
                    if ((lane & 3) == 0) {
                        int r = wm * 32 + mf * 16 + (lane >> 2);
                        ssred[r * 4 + wn] = s0;
                        ssred[(r + 8) * 4 + wn] = s1;
                    }
                }
                __syncthreads();
#pragma unroll
                for (int mf = 0; mf < 2; mf++) {
                    int r = wm * 32 + mf * 16 + (lane >> 2);
                    float t0 = ssred[r * 4] + ssred[r * 4 + 1] + ssred[r * 4 + 2] + ssred[r * 4 + 3];
                    int r1 = r + 8;
                    float t1 = ssred[r1 * 4] + ssred[r1 * 4 + 1] + ssred[r1 * 4 + 2] + ssred[r1 * 4 + 3];
                    scale[mf][0] = 1.f / fmaxf(sqrtf(t0), 1e-12f);
                    scale[mf][1] = 1.f / fmaxf(sqrtf(t1), 1e-12f);
                }
            } else {
#pragma unroll
                for (int mf = 0; mf < 2; mf++) { scale[mf][0] = 1.f; scale[mf][1] = 1.f; }
            }
#pragma unroll
            for (int mf = 0; mf < 2; mf++)
#pragma unroll
                for (int hh = 0; hh < 2; hh++) {
                    int r = m0 + wm * 32 + mf * 16 + (lane >> 2) + hh * 8;
                    if (r < NN) {
#pragma unroll
                        for (int nf = 0; nf < 4; nf++) {
                            int col = wn * 32 + nf * 8 + (lane & 3) * 2;
                            float v0 = acc[mf][nf][2 * hh] * scale[mf][hh];
                            float v1 = acc[mf][nf][2 * hh + 1] * scale[mf][hh];
                            if (writeF)
                                *(float2*)(outF + (size_t)r * HH + col) = make_float2(v0, v1);
                            if (writeB) {
                                __half2 hv, lv;
                                h2pair(v0, v1, hv, lv);
                                *(__half2*)(outH + (size_t)r * HH + col) = hv;
                                *(__half2*)(outL + (size_t)r * HH + col) = lv;
                            }
                        }
                    }
                }
#pragma unroll
            for (int mf = 0; mf < 2; mf++)
#pragma unroll
                for (int nf = 0; nf < 4; nf++)
#pragma unroll
                    for (int q = 0; q < 4; q++) acc[mf][nf][q] = 0.f;
        }
    }
}

// ---------------- global_add_pool (+ re-zero deg for next replay) ----------------
__global__ __launch_bounds__(128) void pool_kernel(const float* __restrict__ h,
                                                   const int* __restrict__ batch,
                                                   float* __restrict__ pool,
                                                   int* __restrict__ deg) {
    int gtid = blockIdx.x * 128 + threadIdx.x;
    for (int i = gtid; i < 3 * NN; i += gridDim.x * 128) deg[i] = 0;
    int c = threadIdx.x;
    int start = blockIdx.x * PCH;
    if (start >= NN) return;
    int end = min(start + PCH, NN);
    int cur = batch[start];
    float acc = 0.f;
    for (int i = start; i < end; ++i) {
        int b = batch[i];
        if (b != cur) { atomicAdd(&pool[cur * HH + c], acc); acc = 0.f; cur = b; }
        acc += h[(size_t)i * HH + c];
    }
    atomicAdd(&pool[cur * HH + c], acc);
}

// ---------------- MLP head ----------------
__global__ __launch_bounds__(256) void mlp_kernel(const float* __restrict__ pool,
                                                  const float* __restrict__ W0, const float* __restrict__ b0,
                                                  const float* __restrict__ W1, const float* __restrict__ b1,
                                                  const float* __restrict__ hW, const float* __restrict__ hb,
                                                  float* __restrict__ out) {
    __shared__ float Gs[GG * HH];
    int tid = threadIdx.x;
    for (int i = tid; i < GG * HH / 4; i += 256)
        ((float4*)Gs)[i] = ((const float4*)pool)[i];
    __syncthreads();
    int c = tid & 127;
    int rb = tid >> 7;
    float s[32];
#pragma unroll
    for (int j = 0; j < 32; j++) s[j] = b0[c];
    for (int k = 0; k < HH; k++) {
        float w = __ldg(W0 + k * HH + c);
#pragma unroll
        for (int j = 0; j < 32; j++) s[j] = fmaf(Gs[(rb + 2 * j) * HH + k], w, s[j]);
    }
    __syncthreads();
#pragma unroll
    for (int j = 0; j < 32; j++) Gs[(rb + 2 * j) * HH + c] = fmaxf(s[j], 0.f);
    __syncthreads();
#pragma unroll
    for (int j = 0; j < 32; j++) s[j] = b1[c];
    for (int k = 0; k < HH; k++) {
        float w = __ldg(W1 + k * HH + c);
#pragma unroll
        for (int j = 0; j < 32; j++) s[j] = fmaf(Gs[(rb + 2 * j) * HH + k], w, s[j]);
    }
    __syncthreads();
#pragma unroll
    for (int j = 0; j < 32; j++) Gs[(rb + 2 * j) * HH + c] = fmaxf(s[j], 0.f);
    __syncthreads();
    if (tid < GG) {
        float acc = hb[0];
        for (int k = 0; k < HH; k++) acc = fmaf(Gs[tid * HH + k], hW[k], acc);
        out[tid] = acc;
    }
}

// ---------------- driver ----------------
extern "C" void kernel_launch(void* const* d_in, const int* in_sizes, int n_in,
                              void* d_out, int out_size) {
    const float* x     = (const float*)d_in[0];
    const int*   eic   = (const int*)d_in[1];
    const int*   eid   = (const int*)d_in[2];
    const int*   eit   = (const int*)d_in[3];
    const int*   batch = (const int*)d_in[4];
    WPtrs wp;
    const float* bl[5];
    for (int i = 0; i < 5; i++) {
        wp.Wl[i] = (const float*)d_in[5 + 3 * i];
        bl[i]    = (const float*)d_in[6 + 3 * i];
        wp.Wr[i] = (const float*)d_in[7 + 3 * i];
    }
    const float* l0W   = (const float*)d_in[20];
    const float* l0b   = (const float*)d_in[21];
    const float* l1W   = (const float*)d_in[22];
    const float* l1b   = (const float*)d_in[23];
    const float* headW = (const float*)d_in[24];
    const float* headb = (const float*)d_in[25];

    void* p;
    cudaGetSymbolAddress(&p, g_bufA); float* bufA = (float*)p;
    cudaGetSymbolAddress(&p, g_pool); float* poolp = (float*)p;
    cudaGetSymbolAddress(&p, g_deg);  int* degp = (int*)p;
    cudaGetSymbolAddress(&p, g_csr);  int* csrp = (int*)p;
    cudaGetSymbolAddress(&p, g_hH);   __half* hH = (__half*)p;
    cudaGetSymbolAddress(&p, g_hL);   __half* hL = (__half*)p;
    cudaGetSymbolAddress(&p, g_aggH); __half* aggH = (__half*)p;
    cudaGetSymbolAddress(&p, g_aggL); __half* aggL = (__half*)p;
    cudaGetSymbolAddress(&p, g_wtb);  __half* wtb = (__half*)p;

    cudaFuncSetAttribute(sage_mma, cudaFuncAttributeMaxDynamicSharedMemorySize, SMEMSZ);

    size_t bufsz = (size_t)NN * HH;
    setup_kernel<<<CB + XB + WB + PB, 256>>>(eid, eic, eit, wp, x,
                                             hH + bufsz, hL + bufsz, wtb, degp, csrp, poolp);

    const int Les[7] = {0, 1, 1, 2, 0, 1, 1};
    const int Lcv[7] = {0, 1, 1, 2, 3, 4, 4};
    const int Lnm[7] = {1, 1, 1, 0, 1, 1, 1};

    for (int li = 0; li < 7; ++li) {
        int es = Les[li], cv = Lcv[li];
        int in = (li + 1) & 1, outi = li & 1;
        agg_kernel<<<(NN + 7) / 8, 256>>>(hH + (size_t)in * bufsz, aggH, aggL,
                                          csrp + (size_t)es * NN * DCAP, degp + es * NN);
        sage_mma<<<148, 512, SMEMSZ>>>(
            aggH, aggL, hH + (size_t)in * bufsz, hL + (size_t)in * bufsz,
            wtb + (size_t)cv * 2 * HH * HH, bl[cv],
            bufA, hH + (size_t)outi * bufsz, hL + (size_t)outi * bufsz,
            Lnm[li], li == 6 ? 1 : 0, li == 6 ? 0 : 1);
    }

    pool_kernel<<<(NN + PCH - 1) / PCH, 128>>>(bufA, batch, poolp, degp);
    mlp_kernel<<<1, 256>>>(poolp, l0W, l0b, l1W, l1b, headW, headb, (float*)d_out);
}